// round 9
// baseline (speedup 1.0000x reference)
#include <cuda_runtime.h>
#include <cuda_bf16.h>
#include <cuda_fp16.h>
#include <math.h>

#define BB 4
#define SS 2048
#define DD 768
#define HH 12
#define HD 64
#define QK_SCALE 0.125f
#define M_TOK (BB*SS)          // 8192
#define KW_D (DD/2)            // 384
#define N_QKV (3*DD)           // 2304

// ---------------- prepacked global scratch ----------------
__device__ unsigned g_xhi[(size_t)M_TOK * KW_D], g_xlo[(size_t)M_TOK * KW_D];
__device__ unsigned g_wqhi[(size_t)KW_D * N_QKV], g_wqlo[(size_t)KW_D * N_QKV]; // [N][KW]
__device__ unsigned g_wohi[(size_t)KW_D * DD],   g_wolo[(size_t)KW_D * DD];     // [N][KW]
__device__ unsigned g_qhi[(size_t)M_TOK * KW_D], g_qlo[(size_t)M_TOK * KW_D];
__device__ unsigned g_khi[(size_t)BB*HH*SS*32],  g_klo[(size_t)BB*HH*SS*32];    // [bh*S+key][32w]
__device__ float    g_v  [(size_t)BB*HH*SS*HD];
__device__ unsigned g_vh [(size_t)BB*HH*HD*(SS/2)];   // f16x2 [bh][d][kp]
__device__ unsigned g_chi[(size_t)M_TOK * KW_D], g_clo[(size_t)M_TOK * KW_D];

// ---------------- helpers ----------------
__device__ __forceinline__ unsigned short f2bf(float x) {
    return __bfloat16_as_ushort(__float2bfloat16(x));
}
__device__ __forceinline__ float bf2f(unsigned short h) {
    return __bfloat162float(__ushort_as_bfloat16(h));
}
__device__ __forceinline__ void splitpack(float x0, float x1,
                                          unsigned& whi, unsigned& wlo) {
    unsigned short h0 = f2bf(x0), h1 = f2bf(x1);
    unsigned short l0 = f2bf(x0 - bf2f(h0)), l1 = f2bf(x1 - bf2f(h1));
    whi = (unsigned)h0 | ((unsigned)h1 << 16);
    wlo = (unsigned)l0 | ((unsigned)l1 << 16);
}
__device__ __forceinline__ void mmabf(float c[4], const unsigned a[4],
                                      unsigned b0, unsigned b1) {
    asm volatile(
        "mma.sync.aligned.m16n8k16.row.col.f32.bf16.bf16.f32 "
        "{%0,%1,%2,%3},{%4,%5,%6,%7},{%8,%9},{%0,%1,%2,%3};"
        : "+f"(c[0]), "+f"(c[1]), "+f"(c[2]), "+f"(c[3])
        : "r"(a[0]), "r"(a[1]), "r"(a[2]), "r"(a[3]), "r"(b0), "r"(b1));
}
__device__ __forceinline__ void mmaf16(float c[4], const unsigned a[4],
                                       unsigned b0, unsigned b1) {
    asm volatile(
        "mma.sync.aligned.m16n8k16.row.col.f32.f16.f16.f32 "
        "{%0,%1,%2,%3},{%4,%5,%6,%7},{%8,%9},{%0,%1,%2,%3};"
        : "+f"(c[0]), "+f"(c[1]), "+f"(c[2]), "+f"(c[3])
        : "r"(a[0]), "r"(a[1]), "r"(a[2]), "r"(a[3]), "r"(b0), "r"(b1));
}
__device__ __forceinline__ void ldsm4(unsigned r[4], unsigned addr) {
    asm volatile("ldmatrix.sync.aligned.m8n8.x4.shared.b16 {%0,%1,%2,%3}, [%4];"
                 : "=r"(r[0]), "=r"(r[1]), "=r"(r[2]), "=r"(r[3]) : "r"(addr));
}
__device__ __forceinline__ void cp16(unsigned dst, const void* src) {
    asm volatile("cp.async.cg.shared.global [%0], [%1], 16;"
                 :: "r"(dst), "l"(src));
}
__device__ __forceinline__ void cp_commit() {
    asm volatile("cp.async.commit_group;");
}
__device__ __forceinline__ unsigned exp2_f16x2(float lo, float hi) {
    unsigned r;
    asm("cvt.rn.f16x2.f32 %0, %1, %2;" : "=r"(r) : "f"(hi), "f"(lo));
    asm("ex2.approx.f16x2 %0, %0;" : "+r"(r));
    return r;
}

// ---------------- convert kernels ----------------
__global__ void conv_A(const float* __restrict__ in, unsigned* __restrict__ hi,
                       unsigned* __restrict__ lo, int nwords)
{
    int i = blockIdx.x * blockDim.x + threadIdx.x;
    if (i < nwords) {
        float2 v = ((const float2*)in)[i];
        unsigned h, l; splitpack(v.x, v.y, h, l);
        hi[i] = h; lo[i] = l;
    }
}
// transpose weights: in [K][N] fp32 -> hi/lo [N][K/2] packed words
__global__ void conv_Wt(const float* __restrict__ in, unsigned* __restrict__ hi,
                        unsigned* __restrict__ lo, int Kk, int N)
{
    int i = blockIdx.x * blockDim.x + threadIdx.x;
    const int KW = Kk / 2;
    if (i < N * KW) {
        int n = i % N, kw = i / N;
        unsigned h, l;
        splitpack(in[(size_t)(2 * kw) * N + n], in[(size_t)(2 * kw + 1) * N + n], h, l);
        hi[(size_t)n * KW + kw] = h;
        lo[(size_t)n * KW + kw] = l;
    }
}
// g_v f32 [bh][key][d] -> g_vh f16x2 [bh][d][kp] (keys 2kp,2kp+1 packed)
__global__ void repackV(int n)
{
    int i = blockIdx.x * blockDim.x + threadIdx.x;
    if (i < n) {
        const int d = i & 63;
        const int kp = (i >> 6) & 1023;
        const int bh = i >> 16;
        const float f0 = g_v[((size_t)bh * SS + 2 * kp)     * HD + d];
        const float f1 = g_v[((size_t)bh * SS + 2 * kp + 1) * HD + d];
        const unsigned u0 = __half_as_ushort(__float2half_rn(f0));
        const unsigned u1 = __half_as_ushort(__float2half_rn(f1));
        g_vh[((size_t)bh * HD + d) * 1024 + kp] = u0 | (u1 << 16);
    }
}

// ---------------------------------------------------------------------------
// Packed GEMM, ldmatrix edition. 128x128 tile, 8 warps x (64x32), k-tile 16.
// A and B both [row][8 words] stride 12 in smem. 12 LDSM : 48 MMA per k-tile.
// ---------------------------------------------------------------------------
#define GAS 12
#define STW 6144                    // 4 * 128*12
#define GEMM_SMEM (3 * STW * 4)     // 73728 B

template<int EPI>
__global__ void __launch_bounds__(256, 2)
gemm_pk(const unsigned* __restrict__ Ahi_g, const unsigned* __restrict__ Alo_g,
        const unsigned* __restrict__ Bhi_g, const unsigned* __restrict__ Blo_g,
        const float* __restrict__ bias, float* __restrict__ C,
        int KWr, int Nn)
{
    extern __shared__ unsigned smw[];
    const unsigned smb = (unsigned)__cvta_generic_to_shared(smw);

    const int t = threadIdx.x, lane = t & 31, warp = t >> 5;
    const int g = lane >> 2, tg = lane & 3;
    const int m0 = blockIdx.y * 128, n0 = blockIdx.x * 128;
    const int wm = (warp >> 2) * 64, wn = (warp & 3) * 32;

    const int arow = t >> 1, ahalf = t & 1;
    const int NT = KWr / 8;

    auto issue = [&](int kt) {
        if (kt < NT) {
            const unsigned sa = smb + (unsigned)(kt % 3) * STW * 4;
            const unsigned so = (arow * GAS + ahalf * 4) * 4;
            const size_t aoff = (size_t)(m0 + arow) * KWr + kt * 8 + ahalf * 4;
            cp16(sa + so,            Ahi_g + aoff);
            cp16(sa + 1536*4 + so,   Alo_g + aoff);
            const size_t boff = (size_t)(n0 + arow) * KWr + kt * 8 + ahalf * 4;
            cp16(sa + 3072*4 + so,   Bhi_g + boff);
            cp16(sa + 4608*4 + so,   Blo_g + boff);
        }
        cp_commit();
    };

    // ldmatrix per-lane word offsets
    const unsigned aw = (wm + (lane & 15)) * GAS + ((lane & 16) ? 4 : 0);
    const unsigned bw = 3072 + (wn + (lane & 7) + ((lane & 16) >> 1)) * GAS
                      + ((lane & 8) ? 4 : 0);

    float acc[4][4][4];
    #pragma unroll
    for (int i = 0; i < 4; i++)
        #pragma unroll
        for (int j = 0; j < 4; j++)
            #pragma unroll
            for (int k = 0; k < 4; k++) acc[i][j][k] = 0.f;

    issue(0); issue(1);

    for (int kt = 0; kt < NT; kt++) {
        asm volatile("cp.async.wait_group 1;");
        __syncthreads();
        issue(kt + 2);

        const unsigned sb4 = smb + (unsigned)(kt % 3) * STW * 4;
        unsigned ah[4][4], al[4][4], bhf[2][4], blf[2][4];
        #pragma unroll
        for (int ma = 0; ma < 4; ma++) {
            ldsm4(ah[ma], sb4 + (aw + ma * 16 * GAS) * 4);
            ldsm4(al[ma], sb4 + (aw + ma * 16 * GAS + 1536) * 4);
        }
        #pragma unroll
        for (int p = 0; p < 2; p++) {
            ldsm4(bhf[p], sb4 + (bw + p * 16 * GAS) * 4);
            ldsm4(blf[p], sb4 + (bw + p * 16 * GAS + 1536) * 4);
        }
        #pragma unroll
        for (int na = 0; na < 4; na++) {
            const unsigned bh0 = bhf[na >> 1][(na & 1) * 2];
            const unsigned bh1 = bhf[na >> 1][(na & 1) * 2 + 1];
            const unsigned bl0 = blf[na >> 1][(na & 1) * 2];
            const unsigned bl1 = blf[na >> 1][(na & 1) * 2 + 1];
            #pragma unroll
            for (int ma = 0; ma < 4; ma++) {
                mmabf(acc[ma][na], ah[ma], bh0, bh1);
                mmabf(acc[ma][na], ah[ma], bl0, bl1);
                mmabf(acc[ma][na], al[ma], bh0, bh1);
            }
        }
    }

    if (EPI == 0) {
        #pragma unroll
        for (int ma = 0; ma < 4; ma++) {
            #pragma unroll
            for (int na = 0; na < 4; na++) {
                const int row = m0 + wm + ma * 16 + g;
                const int col = n0 + wn + na * 8 + 2 * tg;
                const float bx = bias[col], by = bias[col + 1];
                float2 v0 = make_float2(acc[ma][na][0] + bx, acc[ma][na][1] + by);
                float2 v1 = make_float2(acc[ma][na][2] + bx, acc[ma][na][3] + by);
                *(float2*)&C[(size_t)row * Nn + col] = v0;
                *(float2*)&C[(size_t)(row + 8) * Nn + col] = v1;
            }
        }
    } else {
        #pragma unroll
        for (int na = 0; na < 4; na++) {
            const int col = n0 + wn + na * 8 + 2 * tg;
            const int sec = col / DD;
            const int within = col - sec * DD;
            const int h = within >> 6, hd = within & 63;
            #pragma unroll
            for (int ma = 0; ma < 4; ma++) {
                const int r0 = m0 + wm + ma * 16 + g;
                const float a0 = acc[ma][na][0], a1 = acc[ma][na][1];
                const float a2 = acc[ma][na][2], a3 = acc[ma][na][3];
                if (sec == 0) {
                    unsigned hw, lw;
                    splitpack(a0 * QK_SCALE, a1 * QK_SCALE, hw, lw);
                    g_qhi[(size_t)r0 * KW_D + (within >> 1)] = hw;
                    g_qlo[(size_t)r0 * KW_D + (within >> 1)] = lw;
                    splitpack(a2 * QK_SCALE, a3 * QK_SCALE, hw, lw);
                    g_qhi[(size_t)(r0 + 8) * KW_D + (within >> 1)] = hw;
                    g_qlo[(size_t)(r0 + 8) * KW_D + (within >> 1)] = lw;
                } else if (sec == 1) {
                    const int bb = r0 >> 11, key = r0 & (SS - 1);
                    const size_t idx = ((size_t)(bb * HH + h) * SS + key) * 32 + (hd >> 1);
                    unsigned hw, lw;
                    splitpack(a0, a1, hw, lw);
                    g_khi[idx] = hw; g_klo[idx] = lw;
                    splitpack(a2, a3, hw, lw);
                    g_khi[idx + 256] = hw; g_klo[idx + 256] = lw;
                } else {
                    const int bb = r0 >> 11, key = r0 & (SS - 1);
                    const size_t vi = (((size_t)(bb * HH + h)) * SS + key) * HD + hd;
                    *(float2*)&g_v[vi] = make_float2(a0, a1);
                    *(float2*)&g_v[vi + 8 * HD] = make_float2(a2, a3);
                }
            }
        }
    }
}

// ---------------------------------------------------------------------------
// Flash attention, ldmatrix edition. Mq=256/CTA, 8 warps x 32 q rows.
// QK^T bf16 3-term; PV f16 (P = cvt+ex2 f16x2 A-frags, l via ones-MMA).
// smem words: Qlo[256][36] | {Khi,Klo}[2][64][36] | Vh[2][64][36]
// ---------------------------------------------------------------------------
#define QS 36
#define OFF_K   (256*QS)              // 9216
#define KBUFW   (2*64*QS)             // 4608 (hi+lo per buffer)
#define OFF_V   (OFF_K + 2*KBUFW)     // 18432
#define VBUFW   (64*QS)               // 2304
#define ATT_W   (OFF_V + 2*VBUFW)     // 23040
#define ATT_SMEM (ATT_W * 4)          // 92160 B
#define ONE2 0x3C003C00u
#define LOG2E 1.4426950408889634f

__global__ void __launch_bounds__(256, 1)
attn_tc()
{
    extern __shared__ unsigned smu[];
    const unsigned smb = (unsigned)__cvta_generic_to_shared(smu);
    const unsigned* Qhi_st = smu + OFF_K;

    const int t = threadIdx.x, lane = t & 31, warp = t >> 5;
    const int g = lane >> 2, tg = lane & 3;
    const int bh = blockIdx.y, qb = blockIdx.x;
    const int b = bh / HH, h = bh - b * HH;
    const int tok0 = b * SS + qb * 256;

    const int krow = t >> 2, kc0 = (t & 3) * 8;    // staging: 64 rows x 4 chunks

    auto issue_kv = [&](int jb, int buf) {
        const unsigned kb = smb + (OFF_K + buf * KBUFW) * 4;
        const unsigned* khs = g_khi + ((size_t)bh * SS + jb * 64 + krow) * 32 + kc0;
        const unsigned* kls = g_klo + ((size_t)bh * SS + jb * 64 + krow) * 32 + kc0;
        cp16(kb + (krow * QS + kc0) * 4,            khs);
        cp16(kb + (krow * QS + kc0 + 4) * 4,        khs + 4);
        cp16(kb + (2304 + krow * QS + kc0) * 4,     kls);
        cp16(kb + (2304 + krow * QS + kc0 + 4) * 4, kls + 4);
        const unsigned vb = smb + (OFF_V + buf * VBUFW) * 4;
        const unsigned* vs = g_vh + ((size_t)bh * HD + krow) * 1024 + jb * 32 + kc0;
        cp16(vb + (krow * QS + kc0) * 4,     vs);
        cp16(vb + (krow * QS + kc0 + 4) * 4, vs + 4);
    };

    // ---- prologue: Q hi (transient in K region) + Q lo ----
    {
        const size_t qsrc = (size_t)(tok0 + t) * KW_D + h * 32;
        #pragma unroll
        for (int i = 0; i < 8; i++) {
            cp16(smb + ((OFF_K + t * QS) + i * 4) * 4, g_qhi + qsrc + i * 4);
            cp16(smb + (t * QS + i * 4) * 4,           g_qlo + qsrc + i * 4);
        }
        cp_commit();
    }
    asm volatile("cp.async.wait_group 0;");
    __syncthreads();

    unsigned qh[2][4][4];
    #pragma unroll
    for (int ma = 0; ma < 2; ma++)
        #pragma unroll
        for (int c = 0; c < 4; c++) {
            const int base = (warp * 32 + ma * 16 + g) * QS + 8 * c + tg;
            qh[ma][c][0] = Qhi_st[base];      qh[ma][c][1] = Qhi_st[base + 8 * QS];
            qh[ma][c][2] = Qhi_st[base + 4];  qh[ma][c][3] = Qhi_st[base + 8 * QS + 4];
        }
    __syncthreads();
    issue_kv(0, 0);
    cp_commit();

    // ldmatrix per-lane word offsets
    const unsigned qw  = (warp * 32 + (lane & 15)) * QS + ((lane & 16) ? 4 : 0);
    const unsigned krw = ((lane & 7) + ((lane & 16) >> 1)) * QS + ((lane & 8) ? 4 : 0);

    float mrow[2][2];
    float oacc[2][8][4], lfr[2][4];
    #pragma unroll
    for (int ma = 0; ma < 2; ma++) {
        mrow[ma][0] = mrow[ma][1] = -1e30f;
        #pragma unroll
        for (int j = 0; j < 4; j++) lfr[ma][j] = 0.f;
        #pragma unroll
        for (int i = 0; i < 8; i++)
            #pragma unroll
            for (int j = 0; j < 4; j++) oacc[ma][i][j] = 0.f;
    }

    const int NT = SS / 64;
    for (int jb = 0; jb < NT; jb++) {
        asm volatile("cp.async.wait_group 0;");
        __syncthreads();
        if (jb + 1 < NT) {
            issue_kv(jb + 1, (jb + 1) & 1);
            cp_commit();
        }

        const int buf = jb & 1;
        const unsigned kbase = smb + (OFF_K + buf * KBUFW) * 4;
        const unsigned lbase = kbase + 2304 * 4;
        const unsigned vbase = smb + (OFF_V + buf * VBUFW) * 4;

        // ---- S = Q K^T (bf16 3-term) ----
        float sacc[2][8][4];
        #pragma unroll
        for (int ma = 0; ma < 2; ma++)
            #pragma unroll
            for (int i = 0; i < 8; i++)
                #pragma unroll
                for (int j = 0; j < 4; j++) sacc[ma][i][j] = 0.f;

        #pragma unroll
        for (int c = 0; c < 4; c++) {
            unsigned ql[2][4];
            ldsm4(ql[0], smb + (qw + 8 * c) * 4);
            ldsm4(ql[1], smb + (qw + 16 * QS + 8 * c) * 4);
            unsigned kh[4][4], kl[4][4];
            #pragma unroll
            for (int p = 0; p < 4; p++) {
                ldsm4(kh[p], kbase + (krw + p * 16 * QS + 8 * c) * 4);
                ldsm4(kl[p], lbase + (krw + p * 16 * QS + 8 * c) * 4);
            }
            #pragma unroll
            for (int na = 0; na < 8; na++) {
                const unsigned bh0 = kh[na >> 1][(na & 1) * 2];
                const unsigned bh1 = kh[na >> 1][(na & 1) * 2 + 1];
                const unsigned bl0 = kl[na >> 1][(na & 1) * 2];
                const unsigned bl1 = kl[na >> 1][(na & 1) * 2 + 1];
                #pragma unroll
                for (int ma = 0; ma < 2; ma++) {
                    mmabf(sacc[ma][na], qh[ma][c], bh0, bh1);
                    mmabf(sacc[ma][na], qh[ma][c], bl0, bl1);
                    mmabf(sacc[ma][na], ql[ma],    bh0, bh1);
                }
            }
        }

        // ---- online softmax -> P as f16x2 A-frags ----
        unsigned hp[2][8][2];
        #pragma unroll
        for (int ma = 0; ma < 2; ma++) {
            float mnl[2];
            #pragma unroll
            for (int hf = 0; hf < 2; hf++) {
                float rmax = -1e30f;
                #pragma unroll
                for (int na = 0; na < 8; na++)
                    rmax = fmaxf(rmax, fmaxf(sacc[ma][na][2*hf], sacc[ma][na][2*hf+1]));
                rmax = fmaxf(rmax, __shfl_xor_sync(0xffffffffu, rmax, 1));
                rmax = fmaxf(rmax, __shfl_xor_sync(0xffffffffu, rmax, 2));
                const float mn = fmaxf(mrow[ma][hf], rmax);
                const float corr = __expf(mrow[ma][hf] - mn);
                mrow[ma][hf] = mn;
                mnl[hf] = mn * LOG2E;
                lfr[ma][2*hf]   *= corr;
                lfr[ma][2*hf+1] *= corr;
                #pragma unroll
                for (int na = 0; na < 8; na++) {
                    oacc[ma][na][2*hf]   *= corr;
                    oacc[ma][na][2*hf+1] *= corr;
                }
            }
            #pragma unroll
            for (int na = 0; na < 8; na++) {
                const float t0 = fmaf(sacc[ma][na][0], LOG2E, -mnl[0]);
                const float t1 = fmaf(sacc[ma][na][1], LOG2E, -mnl[0]);
                const float t2 = fmaf(sacc[ma][na][2], LOG2E, -mnl[1]);
                const float t3 = fmaf(sacc[ma][na][3], LOG2E, -mnl[1]);
                hp[ma][na][0] = exp2_f16x2(t0, t1);
                hp[ma][na][1] = exp2_f16x2(t2, t3);
            }
        }

        // ---- O += P @ V (f16, ldmatrix B-frags); l += P @ 1 ----
        #pragma unroll
        for (int s = 0; s < 4; s++) {
            unsigned ap[2][4];
            #pragma unroll
            for (int ma = 0; ma < 2; ma++) {
                ap[ma][0] = hp[ma][2*s][0];
                ap[ma][1] = hp[ma][2*s][1];
                ap[ma][2] = hp[ma][2*s+1][0];
                ap[ma][3] = hp[ma][2*s+1][1];
            }
            mmaf16(lfr[0], ap[0], ONE2, ONE2);
            mmaf16(lfr[1], ap[1], ONE2, ONE2);
            unsigned vf[4][4];
            #pragma unroll
            for (int p = 0; p < 4; p++)
                ldsm4(vf[p], vbase + (krw + p * 16 * QS + 8 * s) * 4);
            #pragma unroll
            for (int na = 0; na < 8; na++) {
                const unsigned v0 = vf[na >> 1][(na & 1) * 2];
                const unsigned v1 = vf[na >> 1][(na & 1) * 2 + 1];
                mmaf16(oacc[0][na], ap[0], v0, v1);
                mmaf16(oacc[1][na], ap[1], v0, v1);
            }
        }
    }

    // ---- epilogue: ctx split, GEMM-A layout ----
    #pragma unroll
    for (int ma = 0; ma < 2; ma++) {
        const float inv0 = 1.0f / lfr[ma][0];
        const float inv1 = 1.0f / lfr[ma][2];
        const int tok = tok0 + warp * 32 + ma * 16 + g;
        #pragma unroll
        for (int na = 0; na < 8; na++) {
            const int w = h * 32 + na * 4 + tg;
            unsigned hw, lw;
            splitpack(oacc[ma][na][0] * inv0, oacc[ma][na][1] * inv0, hw, lw);
            g_chi[(size_t)tok * KW_D + w] = hw;
            g_clo[(size_t)tok * KW_D + w] = lw;
            splitpack(oacc[ma][na][2] * inv1, oacc[ma][na][3] * inv1, hw, lw);
            g_chi[(size_t)(tok + 8) * KW_D + w] = hw;
            g_clo[(size_t)(tok + 8) * KW_D + w] = lw;
        }
    }
}

// ---------------------------------------------------------------------------
extern "C" void kernel_launch(void* const* d_in, const int* in_sizes, int n_in,
                              void* d_out, int out_size)
{
    const float* x     = (const float*)d_in[0];
    const float* w_qkv = (const float*)d_in[1];
    const float* w_out = (const float*)d_in[2];
    const float* b_out = (const float*)d_in[3];
    float* out = (float*)d_out;

    unsigned *xhi, *xlo, *wqhi, *wqlo, *wohi, *wolo, *chi, *clo;
    cudaGetSymbolAddress((void**)&xhi,  g_xhi);
    cudaGetSymbolAddress((void**)&xlo,  g_xlo);
    cudaGetSymbolAddress((void**)&wqhi, g_wqhi);
    cudaGetSymbolAddress((void**)&wqlo, g_wqlo);
    cudaGetSymbolAddress((void**)&wohi, g_wohi);
    cudaGetSymbolAddress((void**)&wolo, g_wolo);
    cudaGetSymbolAddress((void**)&chi,  g_chi);
    cudaGetSymbolAddress((void**)&clo,  g_clo);

    cudaFuncSetAttribute(gemm_pk<0>, cudaFuncAttributeMaxDynamicSharedMemorySize, GEMM_SMEM);
    cudaFuncSetAttribute(gemm_pk<1>, cudaFuncAttributeMaxDynamicSharedMemorySize, GEMM_SMEM);
    cudaFuncSetAttribute(attn_tc,    cudaFuncAttributeMaxDynamicSharedMemorySize, ATT_SMEM);

    const int nwx = M_TOK * KW_D;
    conv_A<<<(nwx + 255) / 256, 256>>>(x, xhi, xlo, nwx);
    const int nwq = N_QKV * KW_D;
    conv_Wt<<<(nwq + 255) / 256, 256>>>(w_qkv, wqhi, wqlo, DD, N_QKV);
    const int nwo = DD * KW_D;
    conv_Wt<<<(nwo + 255) / 256, 256>>>(w_out, wohi, wolo, DD, DD);

    gemm_pk<1><<<dim3(N_QKV / 128, M_TOK / 128), 256, GEMM_SMEM>>>(
        xhi, xlo, wqhi, wqlo, nullptr, nullptr, KW_D, N_QKV);

    const int nv = BB * HH * HD * (SS / 2);
    repackV<<<(nv + 255) / 256, 256>>>(nv);

    attn_tc<<<dim3(SS / 256, BB * HH), 256, ATT_SMEM>>>();

    gemm_pk<0><<<dim3(DD / 128, M_TOK / 128), 256, GEMM_SMEM>>>(
        chi, clo, wohi, wolo, b_out, out, KW_D, DD);
}

// round 10
// speedup vs baseline: 1.0449x; 1.0449x over previous
#include <cuda_runtime.h>
#include <cuda_bf16.h>
#include <cuda_fp16.h>
#include <math.h>

#define BB 4
#define SS 2048
#define DD 768
#define HH 12
#define HD 64
#define QK_SCALE 0.125f
#define M_TOK (BB*SS)          // 8192
#define KW_D (DD/2)            // 384
#define N_QKV (3*DD)           // 2304

// ---------------- prepacked global scratch ----------------
__device__ unsigned g_xhi[(size_t)M_TOK * KW_D], g_xlo[(size_t)M_TOK * KW_D];
__device__ unsigned g_wqhi[(size_t)KW_D * N_QKV], g_wqlo[(size_t)KW_D * N_QKV];
__device__ unsigned g_wohi[(size_t)KW_D * DD],   g_wolo[(size_t)KW_D * DD];
__device__ unsigned g_qhi[(size_t)M_TOK * KW_D], g_qlo[(size_t)M_TOK * KW_D];
__device__ unsigned g_khi[(size_t)BB*HH*32*SS],  g_klo[(size_t)BB*HH*32*SS];
__device__ float    g_v  [(size_t)BB*HH*SS*HD];
__device__ unsigned g_vh [(size_t)BB*HH*(SS/2)*HD];   // f16x2, keys paired
__device__ unsigned g_chi[(size_t)M_TOK * KW_D], g_clo[(size_t)M_TOK * KW_D];

// ---------------- helpers ----------------
__device__ __forceinline__ unsigned short f2bf(float x) {
    return __bfloat16_as_ushort(__float2bfloat16(x));
}
__device__ __forceinline__ float bf2f(unsigned short h) {
    return __bfloat162float(__ushort_as_bfloat16(h));
}
__device__ __forceinline__ void splitpack(float x0, float x1,
                                          unsigned& whi, unsigned& wlo) {
    unsigned short h0 = f2bf(x0), h1 = f2bf(x1);
    unsigned short l0 = f2bf(x0 - bf2f(h0)), l1 = f2bf(x1 - bf2f(h1));
    whi = (unsigned)h0 | ((unsigned)h1 << 16);
    wlo = (unsigned)l0 | ((unsigned)l1 << 16);
}
// NOTE: not volatile — pure register ops, lets ptxas schedule freely.
__device__ __forceinline__ void mmabf(float c[4], const unsigned a[4],
                                      unsigned b0, unsigned b1) {
    asm("mma.sync.aligned.m16n8k16.row.col.f32.bf16.bf16.f32 "
        "{%0,%1,%2,%3},{%4,%5,%6,%7},{%8,%9},{%0,%1,%2,%3};"
        : "+f"(c[0]), "+f"(c[1]), "+f"(c[2]), "+f"(c[3])
        : "r"(a[0]), "r"(a[1]), "r"(a[2]), "r"(a[3]), "r"(b0), "r"(b1));
}
__device__ __forceinline__ void mmaf16(float c[4], const unsigned a[4],
                                       unsigned b0, unsigned b1) {
    asm("mma.sync.aligned.m16n8k16.row.col.f32.f16.f16.f32 "
        "{%0,%1,%2,%3},{%4,%5,%6,%7},{%8,%9},{%0,%1,%2,%3};"
        : "+f"(c[0]), "+f"(c[1]), "+f"(c[2]), "+f"(c[3])
        : "r"(a[0]), "r"(a[1]), "r"(a[2]), "r"(a[3]), "r"(b0), "r"(b1));
}
__device__ __forceinline__ void cp16(unsigned dst, const void* src) {
    asm volatile("cp.async.cg.shared.global [%0], [%1], 16;"
                 :: "r"(dst), "l"(src));
}
__device__ __forceinline__ void cp_commit() {
    asm volatile("cp.async.commit_group;");
}
__device__ __forceinline__ unsigned exp2_f16x2(float lo, float hi) {
    unsigned r;
    asm("cvt.rn.f16x2.f32 %0, %1, %2;" : "=r"(r) : "f"(hi), "f"(lo));
    asm("ex2.approx.f16x2 %0, %0;" : "+r"(r));
    return r;
}

// ---------------- convert kernels ----------------
__global__ void conv_A(const float* __restrict__ in, unsigned* __restrict__ hi,
                       unsigned* __restrict__ lo, int nwords)
{
    int i = blockIdx.x * blockDim.x + threadIdx.x;
    if (i < nwords) {
        float2 v = ((const float2*)in)[i];
        unsigned h, l; splitpack(v.x, v.y, h, l);
        hi[i] = h; lo[i] = l;
    }
}
__global__ void conv_B(const float* __restrict__ in, unsigned* __restrict__ hi,
                       unsigned* __restrict__ lo, int KWr, int N)
{
    int i = blockIdx.x * blockDim.x + threadIdx.x;
    if (i < KWr * N) {
        int kw = i / N, n = i - kw * N;
        unsigned h, l;
        splitpack(in[(size_t)(2*kw) * N + n], in[(size_t)(2*kw+1) * N + n], h, l);
        hi[i] = h; lo[i] = l;
    }
}
// g_v f32 [row][d] -> g_vh f16x2 word[(bh*1024+kp)][d] packing keys (2kp, 2kp+1)
__global__ void repackV(int n)
{
    int i = blockIdx.x * blockDim.x + threadIdx.x;
    if (i < n) {
        const int d = i & 63;
        const size_t q = (size_t)(i >> 6);
        const float f0 = g_v[q * 128 + d];
        const float f1 = g_v[q * 128 + 64 + d];
        const unsigned u0 = __half_as_ushort(__float2half_rn(f0));
        const unsigned u1 = __half_as_ushort(__float2half_rn(f1));
        g_vh[i] = u0 | (u1 << 16);
    }
}

// ---------------------------------------------------------------------------
// Packed-operand GEMM (round-5 dataflow): 128x128 tile, 8 warps x (64x32),
// k-tile 16, 3-stage cp.async. Term-major MMA order (dep distance 4).
// ---------------------------------------------------------------------------
#define GAS 12
#define GBS 136
#define STW 5248
#define GEMM_SMEM (3 * STW * 4)

template<int EPI>
__global__ void __launch_bounds__(256, 2)
gemm_pk(const unsigned* __restrict__ Ahi_g, const unsigned* __restrict__ Alo_g,
        const unsigned* __restrict__ Bhi_g, const unsigned* __restrict__ Blo_g,
        const float* __restrict__ bias, float* __restrict__ C,
        int KWr, int Nn)
{
    extern __shared__ unsigned smw[];
    const unsigned smb = (unsigned)__cvta_generic_to_shared(smw);

    const int t = threadIdx.x, lane = t & 31, warp = t >> 5;
    const int g = lane >> 2, tg = lane & 3;
    const int m0 = blockIdx.y * 128, n0 = blockIdx.x * 128;
    const int wm = (warp >> 2) * 64, wn = (warp & 3) * 32;

    const int arow = t >> 1, ahalf = t & 1;
    const int bkw = t >> 5, bc = (t & 31) * 4;

    const int NT = KWr / 8;

    auto issue = [&](int kt) {
        if (kt < NT) {
            const unsigned sa = smb + (unsigned)(kt % 3) * STW * 4;
            const size_t aoff = (size_t)(m0 + arow) * KWr + kt * 8 + ahalf * 4;
            cp16(sa + (arow * GAS + ahalf * 4) * 4,        Ahi_g + aoff);
            cp16(sa + (1536 + arow * GAS + ahalf * 4) * 4, Alo_g + aoff);
            const size_t boff = (size_t)(kt * 8 + bkw) * Nn + n0 + bc;
            cp16(sa + (3072 + bkw * GBS + bc) * 4,         Bhi_g + boff);
            cp16(sa + (4160 + bkw * GBS + bc) * 4,         Blo_g + boff);
        }
        cp_commit();
    };

    float acc[4][4][4];
    #pragma unroll
    for (int i = 0; i < 4; i++)
        #pragma unroll
        for (int j = 0; j < 4; j++)
            #pragma unroll
            for (int k = 0; k < 4; k++) acc[i][j][k] = 0.f;

    issue(0); issue(1);

    for (int kt = 0; kt < NT; kt++) {
        asm volatile("cp.async.wait_group 1;");
        __syncthreads();
        issue(kt + 2);

        const unsigned* SA_hi = smw + (kt % 3) * STW;
        const unsigned* SA_lo = SA_hi + 1536;
        const unsigned* SB_hi = SA_hi + 3072;
        const unsigned* SB_lo = SA_hi + 4160;

        unsigned ah[4][4], al[4][4];
        #pragma unroll
        for (int ma = 0; ma < 4; ma++) {
            const int base = (wm + ma * 16 + g) * GAS + tg;
            ah[ma][0] = SA_hi[base];      ah[ma][1] = SA_hi[base + 8 * GAS];
            ah[ma][2] = SA_hi[base + 4];  ah[ma][3] = SA_hi[base + 8 * GAS + 4];
            al[ma][0] = SA_lo[base];      al[ma][1] = SA_lo[base + 8 * GAS];
            al[ma][2] = SA_lo[base + 4];  al[ma][3] = SA_lo[base + 8 * GAS + 4];
        }
        #pragma unroll
        for (int na = 0; na < 4; na++) {
            const int col = wn + na * 8 + g;
            const unsigned bh0 = SB_hi[tg * GBS + col];
            const unsigned bh1 = SB_hi[(tg + 4) * GBS + col];
            const unsigned bl0 = SB_lo[tg * GBS + col];
            const unsigned bl1 = SB_lo[(tg + 4) * GBS + col];
            // term-major: each accumulator's 3 MMAs are 4 apart, not adjacent
            #pragma unroll
            for (int ma = 0; ma < 4; ma++) mmabf(acc[ma][na], ah[ma], bh0, bh1);
            #pragma unroll
            for (int ma = 0; ma < 4; ma++) mmabf(acc[ma][na], ah[ma], bl0, bl1);
            #pragma unroll
            for (int ma = 0; ma < 4; ma++) mmabf(acc[ma][na], al[ma], bh0, bh1);
        }
    }

    if (EPI == 0) {
        #pragma unroll
        for (int ma = 0; ma < 4; ma++) {
            #pragma unroll
            for (int na = 0; na < 4; na++) {
                const int row = m0 + wm + ma * 16 + g;
                const int col = n0 + wn + na * 8 + 2 * tg;
                const float bx = bias[col], by = bias[col + 1];
                float2 v0 = make_float2(acc[ma][na][0] + bx, acc[ma][na][1] + by);
                float2 v1 = make_float2(acc[ma][na][2] + bx, acc[ma][na][3] + by);
                *(float2*)&C[(size_t)row * Nn + col] = v0;
                *(float2*)&C[(size_t)(row + 8) * Nn + col] = v1;
            }
        }
    } else {
        #pragma unroll
        for (int na = 0; na < 4; na++) {
            const int col = n0 + wn + na * 8 + 2 * tg;
            const int sec = col / DD;
            const int within = col - sec * DD;
            const int h = within >> 6, hd = within & 63;
            #pragma unroll
            for (int ma = 0; ma < 4; ma++) {
                const int r0 = m0 + wm + ma * 16 + g;
                const float a0 = acc[ma][na][0], a1 = acc[ma][na][1];
                const float a2 = acc[ma][na][2], a3 = acc[ma][na][3];
                if (sec == 0) {
                    unsigned hw, lw;
                    splitpack(a0 * QK_SCALE, a1 * QK_SCALE, hw, lw);
                    g_qhi[(size_t)r0 * KW_D + (within >> 1)] = hw;
                    g_qlo[(size_t)r0 * KW_D + (within >> 1)] = lw;
                    splitpack(a2 * QK_SCALE, a3 * QK_SCALE, hw, lw);
                    g_qhi[(size_t)(r0 + 8) * KW_D + (within >> 1)] = hw;
                    g_qlo[(size_t)(r0 + 8) * KW_D + (within >> 1)] = lw;
                } else if (sec == 1) {
                    const int bh = (r0 >> 11) * HH + h, key = r0 & (SS - 1);
                    const size_t idx = ((size_t)bh * 32 + (hd >> 1)) * SS + key;
                    unsigned hw, lw;
                    splitpack(a0, a1, hw, lw);
                    g_khi[idx] = hw; g_klo[idx] = lw;
                    splitpack(a2, a3, hw, lw);
                    g_khi[idx + 8] = hw; g_klo[idx + 8] = lw;
                } else {
                    const int bh = (r0 >> 11) * HH + h, key = r0 & (SS - 1);
                    const size_t vi = ((size_t)bh * SS + key) * HD + hd;
                    *(float2*)&g_v[vi] = make_float2(a0, a1);
                    *(float2*)&g_v[vi + 8 * HD] = make_float2(a2, a3);
                }
            }
        }
    }
}

// ---------------------------------------------------------------------------
// Flash attention (round-8 base): Mq=256/CTA, 8 warps x 32 q rows.
// QK^T bf16 3-term with term-major scheduling over na-pairs (dep distance 4).
// PV: P as f16x2 (cvt+ex2) = f16 A-frags; l via ones-MMA. No shuffles in PV.
// smem words: Qlo[256][36] | {Khi,Klo}[2][32][72] | Vh[2][32][72]
// ---------------------------------------------------------------------------
#define QS 36
#define KS 72
#define VS 72
#define OFF_K   (256*QS)              // 9216
#define KBUFW   (2*32*KS)             // 4608
#define OFF_V   (OFF_K + 2*KBUFW)     // 18432
#define VBUFW   (32*VS)               // 2304
#define ATT_W   (OFF_V + 2*VBUFW)     // 23040
#define ATT_SMEM (ATT_W * 4)          // 92160 B
#define ONE2 0x3C003C00u
#define LOG2E 1.4426950408889634f

__global__ void __launch_bounds__(256, 1)
attn_tc()
{
    extern __shared__ unsigned smu[];
    const unsigned smb = (unsigned)__cvta_generic_to_shared(smu);
    const unsigned* Qlo = smu;

    const int t = threadIdx.x, lane = t & 31, warp = t >> 5;
    const int g = lane >> 2, tg = lane & 3;
    const int bh = blockIdx.y, qb = blockIdx.x;
    const int b = bh / HH, h = bh - b * HH;
    const int tok0 = b * SS + qb * 256;

    const int kdw = t >> 3, kc = (t & 7) * 8;
    const int vkp = t >> 3, vch = (t & 7) * 4;

    auto issue_kv = [&](int jb, int buf) {
        const unsigned kb = smb + (OFF_K + buf * KBUFW) * 4;
        const unsigned* khs = g_khi + ((size_t)bh * 32 + kdw) * SS + jb * 64 + kc;
        const unsigned* kls = g_klo + ((size_t)bh * 32 + kdw) * SS + jb * 64 + kc;
        cp16(kb + (kdw * KS + kc) * 4,               khs);
        cp16(kb + (kdw * KS + kc + 4) * 4,           khs + 4);
        cp16(kb + (32 * KS + kdw * KS + kc) * 4,     kls);
        cp16(kb + (32 * KS + kdw * KS + kc + 4) * 4, kls + 4);
        const unsigned vb = smb + (OFF_V + buf * VBUFW) * 4;
        const unsigned* vs = g_vh + ((size_t)bh * 1024 + jb * 32 + vkp) * 64 + vch;
        cp16(vb + (vkp * VS + vch) * 4,       vs);
        cp16(vb + (vkp * VS + vch + 32) * 4,  vs + 32);
    };

    // ---- prologue: Q hi (into K region, transient) + Q lo ----
    {
        const size_t qsrc = (size_t)(tok0 + t) * KW_D + h * 32;
        #pragma unroll
        for (int i = 0; i < 8; i++) {
            cp16(smb + ((OFF_K + t * QS) + i * 4) * 4, g_qhi + qsrc + i * 4);
            cp16(smb + (t * QS + i * 4) * 4,           g_qlo + qsrc + i * 4);
        }
        cp_commit();
    }
    asm volatile("cp.async.wait_group 0;");
    __syncthreads();

    unsigned qh[2][4][4];
    {
        const unsigned* Qhi = smu + OFF_K;
        #pragma unroll
        for (int ma = 0; ma < 2; ma++)
            #pragma unroll
            for (int c = 0; c < 4; c++) {
                const int base = (warp * 32 + ma * 16 + g) * QS + 8 * c + tg;
                qh[ma][c][0] = Qhi[base];      qh[ma][c][1] = Qhi[base + 8 * QS];
                qh[ma][c][2] = Qhi[base + 4];  qh[ma][c][3] = Qhi[base + 8 * QS + 4];
            }
    }
    __syncthreads();
    issue_kv(0, 0);
    cp_commit();

    float mrow[2][2];
    float oacc[2][8][4], lfr[2][4];
    #pragma unroll
    for (int ma = 0; ma < 2; ma++) {
        mrow[ma][0] = mrow[ma][1] = -1e30f;
        #pragma unroll
        for (int j = 0; j < 4; j++) lfr[ma][j] = 0.f;
        #pragma unroll
        for (int i = 0; i < 8; i++)
            #pragma unroll
            for (int j = 0; j < 4; j++) oacc[ma][i][j] = 0.f;
    }

    const int NT = SS / 64;
    for (int jb = 0; jb < NT; jb++) {
        asm volatile("cp.async.wait_group 0;");
        __syncthreads();
        if (jb + 1 < NT) {
            issue_kv(jb + 1, (jb + 1) & 1);
            cp_commit();
        }

        const int buf = jb & 1;
        const unsigned* Khi = smu + OFF_K + buf * KBUFW;
        const unsigned* Klo = Khi + 32 * KS;
        const unsigned* Vh  = smu + OFF_V + buf * VBUFW;

        // ---- S = Q K^T (bf16 3-term, term-major over na-pairs) ----
        float sacc[2][8][4];
        #pragma unroll
        for (int ma = 0; ma < 2; ma++)
            #pragma unroll
            for (int i = 0; i < 8; i++)
                #pragma unroll
                for (int j = 0; j < 4; j++) sacc[ma][i][j] = 0.f;

        #pragma unroll
        for (int c = 0; c < 4; c++) {
            unsigned ql[2][4];
            #pragma unroll
            for (int ma = 0; ma < 2; ma++) {
                const int qb2 = (warp * 32 + ma * 16 + g) * QS + 8 * c + tg;
                ql[ma][0] = Qlo[qb2];      ql[ma][1] = Qlo[qb2 + 8 * QS];
                ql[ma][2] = Qlo[qb2 + 4];  ql[ma][3] = Qlo[qb2 + 8 * QS + 4];
            }
            #pragma unroll
            for (int np = 0; np < 4; np++) {
                const int na0 = 2 * np, na1 = 2 * np + 1;
                const int kcA = na0 * 8 + g, kcB = na1 * 8 + g;
                const unsigned Ah0 = Khi[(8 * c + tg)     * KS + kcA];
                const unsigned Ah1 = Khi[(8 * c + tg + 4) * KS + kcA];
                const unsigned Al0 = Klo[(8 * c + tg)     * KS + kcA];
                const unsigned Al1 = Klo[(8 * c + tg + 4) * KS + kcA];
                const unsigned Bh0 = Khi[(8 * c + tg)     * KS + kcB];
                const unsigned Bh1 = Khi[(8 * c + tg + 4) * KS + kcB];
                const unsigned Bl0 = Klo[(8 * c + tg)     * KS + kcB];
                const unsigned Bl1 = Klo[(8 * c + tg + 4) * KS + kcB];
                // term 1 (qhi * khi) across 4 independent accumulators
                mmabf(sacc[0][na0], qh[0][c], Ah0, Ah1);
                mmabf(sacc[1][na0], qh[1][c], Ah0, Ah1);
                mmabf(sacc[0][na1], qh[0][c], Bh0, Bh1);
                mmabf(sacc[1][na1], qh[1][c], Bh0, Bh1);
                // term 2 (qhi * klo)
                mmabf(sacc[0][na0], qh[0][c], Al0, Al1);
                mmabf(sacc[1][na0], qh[1][c], Al0, Al1);
                mmabf(sacc[0][na1], qh[0][c], Bl0, Bl1);
                mmabf(sacc[1][na1], qh[1][c], Bl0, Bl1);
                // term 3 (qlo * khi)
                mmabf(sacc[0][na0], ql[0], Ah0, Ah1);
                mmabf(sacc[1][na0], ql[1], Ah0, Ah1);
                mmabf(sacc[0][na1], ql[0], Bh0, Bh1);
                mmabf(sacc[1][na1], ql[1], Bh0, Bh1);
            }
        }

        // ---- online softmax -> P in f16x2 A-frag form ----
        unsigned hp[2][8][2];
        #pragma unroll
        for (int ma = 0; ma < 2; ma++) {
            float mnl[2];
            #pragma unroll
            for (int hf = 0; hf < 2; hf++) {
                float rmax = -1e30f;
                #pragma unroll
                for (int na = 0; na < 8; na++)
                    rmax = fmaxf(rmax, fmaxf(sacc[ma][na][2*hf], sacc[ma][na][2*hf+1]));
                rmax = fmaxf(rmax, __shfl_xor_sync(0xffffffffu, rmax, 1));
                rmax = fmaxf(rmax, __shfl_xor_sync(0xffffffffu, rmax, 2));
                const float mn = fmaxf(mrow[ma][hf], rmax);
                const float corr = __expf(mrow[ma][hf] - mn);
                mrow[ma][hf] = mn;
                mnl[hf] = mn * LOG2E;
                lfr[ma][2*hf]   *= corr;
                lfr[ma][2*hf+1] *= corr;
                #pragma unroll
                for (int na = 0; na < 8; na++) {
                    oacc[ma][na][2*hf]   *= corr;
                    oacc[ma][na][2*hf+1] *= corr;
                }
            }
            #pragma unroll
            for (int na = 0; na < 8; na++) {
                const float t0 = fmaf(sacc[ma][na][0], LOG2E, -mnl[0]);
                const float t1 = fmaf(sacc[ma][na][1], LOG2E, -mnl[0]);
                const float t2 = fmaf(sacc[ma][na][2], LOG2E, -mnl[1]);
                const float t3 = fmaf(sacc[ma][na][3], LOG2E, -mnl[1]);
                hp[ma][na][0] = exp2_f16x2(t0, t1);   // row g
                hp[ma][na][1] = exp2_f16x2(t2, t3);   // row g+8
            }
        }

        // ---- O += P @ V (f16 MMA); l += P @ 1 ----
        #pragma unroll
        for (int s = 0; s < 4; s++) {
            unsigned ap[2][4];
            #pragma unroll
            for (int ma = 0; ma < 2; ma++) {
                ap[ma][0] = hp[ma][2*s][0];
                ap[ma][1] = hp[ma][2*s][1];
                ap[ma][2] = hp[ma][2*s+1][0];
                ap[ma][3] = hp[ma][2*s+1][1];
            }
            mmaf16(lfr[0], ap[0], ONE2, ONE2);
            mmaf16(lfr[1], ap[1], ONE2, ONE2);
            #pragma unroll
            for (int na = 0; na < 8; na++) {
                const unsigned v0 = Vh[(8*s + tg)     * VS + na * 8 + g];
                const unsigned v1 = Vh[(8*s + 4 + tg) * VS + na * 8 + g];
                mmaf16(oacc[0][na], ap[0], v0, v1);
                mmaf16(oacc[1][na], ap[1], v0, v1);
            }
        }
    }

    // ---- epilogue: ctx split, GEMM-A layout ----
    #pragma unroll
    for (int ma = 0; ma < 2; ma++) {
        const float inv0 = 1.0f / lfr[ma][0];
        const float inv1 = 1.0f / lfr[ma][2];
        const int tok = tok0 + warp * 32 + ma * 16 + g;
        #pragma unroll
        for (int na = 0; na < 8; na++) {
            const int w = h * 32 + na * 4 + tg;
            unsigned hw, lw;
            splitpack(oacc[ma][na][0] * inv0, oacc[ma][na][1] * inv0, hw, lw);
            g_chi[(size_t)tok * KW_D + w] = hw;
            g_clo[(size_t)tok * KW_D + w] = lw;
            splitpack(oacc[ma][na][2] * inv1, oacc[ma][na][3] * inv1, hw, lw);
            g_chi[(size_t)(tok + 8) * KW_D + w] = hw;
            g_clo[(size_t)(tok + 8) * KW_D + w] = lw;
        }
    }
}

// ---------------------------------------------------------------------------
extern "C" void kernel_launch(void* const* d_in, const int* in_sizes, int n_in,
                              void* d_out, int out_size)
{
    const float* x     = (const float*)d_in[0];
    const float* w_qkv = (const float*)d_in[1];
    const float* w_out = (const float*)d_in[2];
    const float* b_out = (const float*)d_in[3];
    float* out = (float*)d_out;

    unsigned *xhi, *xlo, *wqhi, *wqlo, *wohi, *wolo, *chi, *clo;
    cudaGetSymbolAddress((void**)&xhi,  g_xhi);
    cudaGetSymbolAddress((void**)&xlo,  g_xlo);
    cudaGetSymbolAddress((void**)&wqhi, g_wqhi);
    cudaGetSymbolAddress((void**)&wqlo, g_wqlo);
    cudaGetSymbolAddress((void**)&wohi, g_wohi);
    cudaGetSymbolAddress((void**)&wolo, g_wolo);
    cudaGetSymbolAddress((void**)&chi,  g_chi);
    cudaGetSymbolAddress((void**)&clo,  g_clo);

    cudaFuncSetAttribute(gemm_pk<0>, cudaFuncAttributeMaxDynamicSharedMemorySize, GEMM_SMEM);
    cudaFuncSetAttribute(gemm_pk<1>, cudaFuncAttributeMaxDynamicSharedMemorySize, GEMM_SMEM);
    cudaFuncSetAttribute(attn_tc,    cudaFuncAttributeMaxDynamicSharedMemorySize, ATT_SMEM);

    const int nwx = M_TOK * KW_D;
    conv_A<<<(nwx + 255) / 256, 256>>>(x, xhi, xlo, nwx);
    const int nwq = KW_D * N_QKV;
    conv_B<<<(nwq + 255) / 256, 256>>>(w_qkv, wqhi, wqlo, KW_D, N_QKV);
    const int nwo = KW_D * DD;
    conv_B<<<(nwo + 255) / 256, 256>>>(w_out, wohi, wolo, KW_D, DD);

    gemm_pk<1><<<dim3(N_QKV / 128, M_TOK / 128), 256, GEMM_SMEM>>>(
        xhi, xlo, wqhi, wqlo, nullptr, nullptr, KW_D, N_QKV);

    const int nv = BB * HH * (SS / 2) * HD;
    repackV<<<(nv + 255) / 256, 256>>>(nv);

    attn_tc<<<dim3(SS / 256, BB * HH), 256, ATT_SMEM>>>();

    gemm_pk<0><<<dim3(DD / 128, M_TOK / 128), 256, GEMM_SMEM>>>(
        chi, clo, wohi, wolo, b_out, out, KW_D, DD);
}